// round 3
// baseline (speedup 1.0000x reference)
#include <cuda_runtime.h>
#include <cstdint>

// ---------------- problem maxima (bench shapes: T=4096, D=1024, F=2048, E=8, k=2) ---
#define T_MAX 4096
#define E_MAX 8
#define F_MAX 2048
#define D_MAX 1024

typedef unsigned long long ull;

// ---------------- device scratch (alloc-free rule: __device__ globals) -------------
__device__ int   g_counts[E_MAX];
__device__ float g_Psum[E_MAX];
__device__ int   g_asg[E_MAX * T_MAX];                 // per-expert list of assignment ids (t*2+k)
__device__ float g_gates[T_MAX * 2];
__device__ float g_act[(size_t)2 * T_MAX * F_MAX];     // silu(g)*v rows, indexed by assignment id
__device__ float g_ybuf[(size_t)2 * T_MAX * D_MAX];    // raw expert outputs, indexed by assignment id

// ---------------- f32x2 packed-FMA helpers (Blackwell FFMA2) -----------------------
__device__ __forceinline__ ull pk2(float lo, float hi){
  ull r;
  asm("mov.b64 %0, {%1, %2};" : "=l"(r) : "r"(__float_as_uint(lo)), "r"(__float_as_uint(hi)));
  return r;
}
__device__ __forceinline__ ull dup2(float v){
  ull r; unsigned u = __float_as_uint(v);
  asm("mov.b64 %0, {%1, %2};" : "=l"(r) : "r"(u), "r"(u));
  return r;
}
__device__ __forceinline__ void fma2(ull &d, ull a, ull b){
  asm("fma.rn.f32x2 %0, %1, %2, %0;" : "+l"(d) : "l"(a), "l"(b));
}
__device__ __forceinline__ float2 up2(ull v){
  unsigned lo, hi;
  asm("mov.b64 {%0, %1}, %2;" : "=r"(lo), "=r"(hi) : "l"(v));
  float2 f; f.x = __uint_as_float(lo); f.y = __uint_as_float(hi); return f;
}

// ---------------- init ------------------------------------------------------------
__global__ void init_k(){
  int i = threadIdx.x;
  if (i < E_MAX){ g_counts[i] = 0; g_Psum[i] = 0.f; }
}

// ---------------- router: logits, top-2, gates, assignment lists, aux accum --------
__global__ void router_k(const float* __restrict__ x, const float* __restrict__ rw,
                         int T, int E, int D, const int* __restrict__ topk_p){
  int warp = threadIdx.x >> 5, lane = threadIdx.x & 31;
  int t = blockIdx.x * 8 + warp;
  __shared__ float sm_p[8][E_MAX];
  if (lane == 0){
    #pragma unroll
    for (int e = 0; e < E_MAX; e++) sm_p[warp][e] = 0.f;
  }
  if (t < T){
    float acc[E_MAX];
    #pragma unroll
    for (int e = 0; e < E_MAX; e++) acc[e] = 0.f;
    const float* xr = x + (size_t)t * D;
    for (int d = lane; d < D; d += 32){
      float xv = xr[d];
      const float* r = rw + (size_t)d * E;
      #pragma unroll
      for (int e = 0; e < E_MAX; e++) if (e < E) acc[e] += xv * r[e];
    }
    #pragma unroll
    for (int e = 0; e < E_MAX; e++){
      #pragma unroll
      for (int off = 16; off; off >>= 1) acc[e] += __shfl_xor_sync(0xffffffffu, acc[e], off);
    }
    if (lane == 0){
      int tk = topk_p ? *topk_p : 2;
      if (tk < 1) tk = 1; if (tk > 2) tk = 2;
      int i0 = 0; float v0 = acc[0];
      for (int e = 1; e < E; e++) if (acc[e] > v0){ v0 = acc[e]; i0 = e; }
      if (tk == 1){
        g_gates[t*2+0] = 1.f; g_gates[t*2+1] = 0.f;
        int p = atomicAdd(&g_counts[i0], 1);
        g_asg[i0*T_MAX + p] = t*2;
      } else {
        int i1 = -1; float v1 = -3.4e38f;
        for (int e = 0; e < E; e++) if (e != i0 && acc[e] > v1){ v1 = acc[e]; i1 = e; }
        float g1 = 1.f / (1.f + __expf(v0 - v1));   // softmax over {v0, v1}
        float g0 = 1.f - g1;
        g_gates[t*2+0] = g0; g_gates[t*2+1] = g1;
        int p0 = atomicAdd(&g_counts[i0], 1); g_asg[i0*T_MAX + p0] = t*2;
        int p1 = atomicAdd(&g_counts[i1], 1); g_asg[i1*T_MAX + p1] = t*2 + 1;
      }
      // full softmax probs for aux loss
      float m = acc[0];
      for (int e = 1; e < E; e++) m = fmaxf(m, acc[e]);
      float s = 0.f; float pe[E_MAX];
      for (int e = 0; e < E; e++){ pe[e] = __expf(acc[e] - m); s += pe[e]; }
      float inv = 1.f / s;
      for (int e = 0; e < E; e++) sm_p[warp][e] = pe[e] * inv;
    }
  }
  __syncthreads();
  if (threadIdx.x < E){
    float s = 0.f;
    #pragma unroll
    for (int w = 0; w < 8; w++) s += sm_p[w][threadIdx.x];
    atomicAdd(&g_Psum[threadIdx.x], s);
  }
}

// ---------------- aux loss scalar --------------------------------------------------
__global__ void aux_k(float* dst, int T, int E, const int* __restrict__ topk_p){
  if (threadIdx.x == 0 && blockIdx.x == 0){
    int tk = topk_p ? *topk_p : 2;
    if (tk < 1) tk = 1; if (tk > 2) tk = 2;
    float s = 0.f;
    for (int e = 0; e < E; e++){
      float f = (float)g_counts[e] / (float)(T * tk);
      float P = g_Psum[e] / (float)T;
      s += f * P;
    }
    *dst = (float)E * s;
  }
}

// ---------------- gathered GEMM ----------------------------------------------------
// GLU=true : A = gathered x rows [count,K=D], B = w_in[e] cols (n0..n0+63 | F+n0..F+n0+63)
//            epilogue: act[a][n0+j] = silu(g)*v                      (tile 128 x 64, K=D)
// GLU=false: A = gathered act rows [count,K=F], B = w_out[e] cols n0..n0+127
//            epilogue: ybuf[a][n0+j] = raw y                          (tile 128 x 128, K=F)
template<bool GLU>
__global__ __launch_bounds__(256, 2)
void moe_gemm(const float* __restrict__ Asrc, const float* __restrict__ W, int K, int Nout){
  int e = blockIdx.z;
  int count = g_counts[e];
  int m0 = blockIdx.y * 128;
  if (m0 >= count) return;
  int n0 = blockIdx.x * (GLU ? 64 : 128);
  int tid = threadIdx.x;
  int tx = tid & 15, ty = tid >> 4;

  __shared__ float As[16][132];   // [kk][m], padded against STS conflicts
  __shared__ float Bs[16][128];   // [kk][n] combined (GLU: 64 g | 64 v)

  const float* Abase = GLU ? Asrc : g_act;

  // per-thread A-gather rows (fixed across k loop)
  int ar0 = tid >> 2, ar1 = ar0 + 64;
  int c4 = (tid & 3) * 4;
  const float* Arow0 = nullptr; const float* Arow1 = nullptr;
  {
    int mg = m0 + ar0;
    if (mg < count){
      int a = g_asg[e*T_MAX + mg];
      Arow0 = Abase + (size_t)(GLU ? (a >> 1) : a) * (size_t)K + c4;
    }
    mg = m0 + ar1;
    if (mg < count){
      int a = g_asg[e*T_MAX + mg];
      Arow1 = Abase + (size_t)(GLU ? (a >> 1) : a) * (size_t)K + c4;
    }
  }

  // per-thread B pointers
  int rb = tid >> 4, cb = tid & 15;
  const float* Wp0; const float* Wp1; size_t wstep;
  if (GLU){
    size_t rowlen = 2 * (size_t)Nout;                       // w_in row = 2F
    const float* wbase = W + ((size_t)e * K + rb) * rowlen;
    Wp0 = wbase + n0 + cb*4;                                // g half
    Wp1 = wbase + Nout + n0 + cb*4;                         // v half
    wstep = 16 * rowlen;
  } else {
    size_t rowlen = (size_t)Nout;                           // w_out row = D
    const float* wbase = W + ((size_t)e * K + rb) * rowlen;
    Wp0 = wbase + n0 + cb*4;
    Wp1 = wbase + n0 + 64 + cb*4;
    wstep = 16 * rowlen;
  }

  ull acc[4][8];
  {
    ull z = pk2(0.f, 0.f);
    #pragma unroll
    for (int i = 0; i < 4; i++)
      #pragma unroll
      for (int j = 0; j < 8; j++) acc[i][j] = z;
  }

  int mbase = ty * 8;
  int jb0 = GLU ? tx*4       : tx*8;
  int jb1 = GLU ? 64 + tx*4  : tx*8 + 4;

  const float4 z4 = make_float4(0.f, 0.f, 0.f, 0.f);
  float4 a0 = Arow0 ? *(const float4*)(Arow0) : z4;
  float4 a1 = Arow1 ? *(const float4*)(Arow1) : z4;
  float4 b0 = *(const float4*)Wp0;
  float4 b1 = *(const float4*)Wp1;

  for (int k0 = 0; k0 < K; k0 += 16){
    __syncthreads();
    As[c4+0][ar0] = a0.x; As[c4+1][ar0] = a0.y; As[c4+2][ar0] = a0.z; As[c4+3][ar0] = a0.w;
    As[c4+0][ar1] = a1.x; As[c4+1][ar1] = a1.y; As[c4+2][ar1] = a1.z; As[c4+3][ar1] = a1.w;
    *(float4*)&Bs[rb][cb*4]      = b0;
    *(float4*)&Bs[rb][64 + cb*4] = b1;
    __syncthreads();
    if (k0 + 16 < K){                       // software-pipeline next tile's gmem loads
      a0 = Arow0 ? *(const float4*)(Arow0 + k0 + 16) : z4;
      a1 = Arow1 ? *(const float4*)(Arow1 + k0 + 16) : z4;
      Wp0 += wstep; Wp1 += wstep;
      b0 = *(const float4*)Wp0;
      b1 = *(const float4*)Wp1;
    }
    #pragma unroll
    for (int kk = 0; kk < 16; kk++){
      float4 aA = *(const float4*)&As[kk][mbase];
      float4 aB = *(const float4*)&As[kk][mbase + 4];
      float4 bx = *(const float4*)&Bs[kk][jb0];
      float4 by = *(const float4*)&Bs[kk][jb1];
      ull ap[4] = { pk2(aA.x, aA.y), pk2(aA.z, aA.w), pk2(aB.x, aB.y), pk2(aB.z, aB.w) };
      ull bd[8] = { dup2(bx.x), dup2(bx.y), dup2(bx.z), dup2(bx.w),
                    dup2(by.x), dup2(by.y), dup2(by.z), dup2(by.w) };
      #pragma unroll
      for (int n = 0; n < 8; n++)
        #pragma unroll
        for (int mp = 0; mp < 4; mp++)
          fma2(acc[mp][n], ap[mp], bd[n]);
    }
  }

  #pragma unroll
  for (int r = 0; r < 8; r++){
    int mg = m0 + mbase + r;
    if (mg >= count) continue;
    int a = g_asg[e*T_MAX + mg];
    int r2 = r >> 1; int hi = r & 1;
    float vals[8];
    #pragma unroll
    for (int n = 0; n < 8; n++){
      float2 p = up2(acc[r2][n]);
      vals[n] = hi ? p.y : p.x;
    }
    if (GLU){
      float4 o;
      #pragma unroll
      for (int i = 0; i < 4; i++){
        float g = vals[i], v = vals[4 + i];
        float s = g / (1.f + __expf(-g));       // silu
        ((float*)&o)[i] = s * v;
      }
      *(float4*)(g_act + (size_t)a * Nout + n0 + tx*4) = o;
    } else {
      float4 o0, o1;
      #pragma unroll
      for (int i = 0; i < 4; i++){ ((float*)&o0)[i] = vals[i]; ((float*)&o1)[i] = vals[4 + i]; }
      float* dst = g_ybuf + (size_t)a * Nout + n0 + tx*8;
      *(float4*)dst       = o0;
      *(float4*)(dst + 4) = o1;
    }
  }
}

// ---------------- deterministic combine: out = bias + sum_k gate_k * y_k -----------
__global__ void combine_k(const float* __restrict__ bias, float* __restrict__ out,
                          int T, int D, const int* __restrict__ topk_p){
  int t = blockIdx.x;
  int tk = topk_p ? *topk_p : 2;
  if (tk < 1) tk = 1; if (tk > 2) tk = 2;
  for (int c = threadIdx.x * 4; c < D; c += 256 * 4){
    float4 o = *(const float4*)(bias + c);
    #pragma unroll
    for (int k = 0; k < 2; k++){
      if (k < tk){
        float g = g_gates[t*2 + k];
        float4 y = *(const float4*)(g_ybuf + (size_t)(t*2 + k) * D + c);
        o.x += g * y.x; o.y += g * y.y; o.z += g * y.z; o.w += g * y.w;
      }
    }
    *(float4*)(out + (size_t)t * D + c) = o;
  }
}

// ---------------- launch -----------------------------------------------------------
extern "C" void kernel_launch(void* const* d_in, const int* in_sizes, int n_in,
                              void* d_out, int out_size){
  const float* x     = (const float*)d_in[0];
  const float* rw    = (const float*)d_in[1];
  const float* w_in  = (const float*)d_in[2];
  const float* w_out = (const float*)d_in[3];
  const float* bias  = (const float*)d_in[4];
  const int*   topk  = (n_in >= 6) ? (const int*)d_in[5] : nullptr;

  int D = in_sizes[4];
  int T = in_sizes[0] / D;
  int E = in_sizes[1] / D;
  int F = in_sizes[2] / (2 * D * E);
  float* out = (float*)d_out;

  init_k<<<1, 32>>>();
  router_k<<<(T + 7) / 8, 256>>>(x, rw, T, E, D, topk);
  if (out_size > T * D) aux_k<<<1, 1>>>(out + (size_t)T * D, T, E, topk);

  dim3 g1((F + 63) / 64,  (T + 127) / 128, E);
  moe_gemm<true><<<g1, 256>>>(x, w_in, D, F);

  dim3 g2((D + 127) / 128, (T + 127) / 128, E);
  moe_gemm<false><<<g2, 256>>>(x /*unused*/, w_out, F, D);

  combine_k<<<T, 256>>>(bias, out, T, D, topk);
}

// round 5
// speedup vs baseline: 1.6353x; 1.6353x over previous
#include <cuda_runtime.h>
#include <cuda_bf16.h>
#include <cstdint>

#define T_MAX 4096
#define E_MAX 8
#define F_MAXC 2048
#define D_MAXC 1024

typedef unsigned int u32;
typedef unsigned short u16;

// ---------------- device scratch ---------------------------------------------------
__device__ int   g_counts[E_MAX];
__device__ float g_Psum[E_MAX];
__device__ int   g_asg[E_MAX * T_MAX];
__device__ float g_gates[T_MAX * 2];
__device__ __nv_bfloat16 g_xhi [(size_t)T_MAX * D_MAXC];
__device__ __nv_bfloat16 g_xlo [(size_t)T_MAX * D_MAXC];
__device__ __nv_bfloat16 g_acthi[(size_t)2 * T_MAX * F_MAXC];
__device__ __nv_bfloat16 g_actlo[(size_t)2 * T_MAX * F_MAXC];
__device__ __nv_bfloat16 g_winhi [(size_t)E_MAX * D_MAXC * 2 * F_MAXC];  // [e][D][2F] interleaved (g,v)
__device__ __nv_bfloat16 g_winlo [(size_t)E_MAX * D_MAXC * 2 * F_MAXC];
__device__ __nv_bfloat16 g_wouthi[(size_t)E_MAX * F_MAXC * D_MAXC];      // [e][F][D]
__device__ __nv_bfloat16 g_woutlo[(size_t)E_MAX * F_MAXC * D_MAXC];
__device__ float g_ybuf[(size_t)2 * T_MAX * D_MAXC];

// ---------------- helpers ----------------------------------------------------------
__device__ __forceinline__ u32 s2u(const void* p){
  u32 a; asm("{ .reg .u64 t; cvta.to.shared.u64 t, %1; cvt.u32.u64 %0, t; }" : "=r"(a) : "l"(p));
  return a;
}
__device__ __forceinline__ u32 pack2h(float a, float b){  // (bf16(a), bf16(b)) in one word
  return (u32)__bfloat16_as_ushort(__float2bfloat16(a)) |
         ((u32)__bfloat16_as_ushort(__float2bfloat16(b)) << 16);
}
__device__ __forceinline__ void cp16(u32 dst, const void* src, bool v){
  int sz = v ? 16 : 0;
  asm volatile("cp.async.cg.shared.global [%0], [%1], 16, %2;" :: "r"(dst), "l"(src), "r"(sz) : "memory");
}
#define CP_COMMIT() asm volatile("cp.async.commit_group;" ::: "memory")
#define CP_WAIT1()  asm volatile("cp.async.wait_group 1;" ::: "memory")

#define LDMX4(r, addr) \
  asm volatile("ldmatrix.sync.aligned.m8n8.x4.shared.b16 {%0,%1,%2,%3}, [%4];" \
    : "=r"((r)[0]), "=r"((r)[1]), "=r"((r)[2]), "=r"((r)[3]) : "r"(addr))
#define LDMX4T(r, addr) \
  asm volatile("ldmatrix.sync.aligned.m8n8.x4.trans.shared.b16 {%0,%1,%2,%3}, [%4];" \
    : "=r"((r)[0]), "=r"((r)[1]), "=r"((r)[2]), "=r"((r)[3]) : "r"(addr))
#define MMA_BF16(c, a, b0, b1) \
  asm volatile("mma.sync.aligned.m16n8k16.row.col.f32.bf16.bf16.f32 " \
    "{%0,%1,%2,%3}, {%4,%5,%6,%7}, {%8,%9}, {%0,%1,%2,%3};" \
    : "+f"((c)[0]), "+f"((c)[1]), "+f"((c)[2]), "+f"((c)[3]) \
    : "r"((a)[0]), "r"((a)[1]), "r"((a)[2]), "r"((a)[3]), "r"(b0), "r"(b1))

// ---------------- init -------------------------------------------------------------
__global__ void init_k(){
  int i = threadIdx.x;
  if (i < E_MAX){ g_counts[i] = 0; g_Psum[i] = 0.f; }
}

// ---------------- router (proven) --------------------------------------------------
__global__ void router_k(const float* __restrict__ x, const float* __restrict__ rw,
                         int T, int E, int D, const int* __restrict__ topk_p){
  int warp = threadIdx.x >> 5, lane = threadIdx.x & 31;
  int t = blockIdx.x * 8 + warp;
  __shared__ float sm_p[8][E_MAX];
  if (lane == 0){
    #pragma unroll
    for (int e = 0; e < E_MAX; e++) sm_p[warp][e] = 0.f;
  }
  if (t < T){
    float acc[E_MAX];
    #pragma unroll
    for (int e = 0; e < E_MAX; e++) acc[e] = 0.f;
    const float* xr = x + (size_t)t * D;
    for (int d = lane; d < D; d += 32){
      float xv = xr[d];
      const float* r = rw + (size_t)d * E;
      #pragma unroll
      for (int e = 0; e < E_MAX; e++) if (e < E) acc[e] += xv * r[e];
    }
    #pragma unroll
    for (int e = 0; e < E_MAX; e++){
      #pragma unroll
      for (int off = 16; off; off >>= 1) acc[e] += __shfl_xor_sync(0xffffffffu, acc[e], off);
    }
    if (lane == 0){
      int tk = topk_p ? *topk_p : 2;
      if (tk < 1) tk = 1; if (tk > 2) tk = 2;
      int i0 = 0; float v0 = acc[0];
      for (int e = 1; e < E; e++) if (acc[e] > v0){ v0 = acc[e]; i0 = e; }
      if (tk == 1){
        g_gates[t*2+0] = 1.f; g_gates[t*2+1] = 0.f;
        int p = atomicAdd(&g_counts[i0], 1);
        g_asg[i0*T_MAX + p] = t*2;
      } else {
        int i1 = -1; float v1 = -3.4e38f;
        for (int e = 0; e < E; e++) if (e != i0 && acc[e] > v1){ v1 = acc[e]; i1 = e; }
        float g1 = 1.f / (1.f + __expf(v0 - v1));
        float g0 = 1.f - g1;
        g_gates[t*2+0] = g0; g_gates[t*2+1] = g1;
        int p0 = atomicAdd(&g_counts[i0], 1); g_asg[i0*T_MAX + p0] = t*2;
        int p1 = atomicAdd(&g_counts[i1], 1); g_asg[i1*T_MAX + p1] = t*2 + 1;
      }
      float m = acc[0];
      for (int e = 1; e < E; e++) m = fmaxf(m, acc[e]);
      float s = 0.f; float pe[E_MAX];
      for (int e = 0; e < E; e++){ pe[e] = __expf(acc[e] - m); s += pe[e]; }
      float inv = 1.f / s;
      for (int e = 0; e < E; e++) sm_p[warp][e] = pe[e] * inv;
    }
  }
  __syncthreads();
  if (threadIdx.x < E){
    float s = 0.f;
    #pragma unroll
    for (int w = 0; w < 8; w++) s += sm_p[w][threadIdx.x];
    atomicAdd(&g_Psum[threadIdx.x], s);
  }
}

__global__ void aux_k(float* dst, int T, int E, const int* __restrict__ topk_p){
  if (threadIdx.x == 0 && blockIdx.x == 0){
    int tk = topk_p ? *topk_p : 2;
    if (tk < 1) tk = 1; if (tk > 2) tk = 2;
    float s = 0.f;
    for (int e = 0; e < E; e++){
      float f = (float)g_counts[e] / (float)(T * tk);
      float P = g_Psum[e] / (float)T;
      s += f * P;
    }
    *dst = (float)E * s;
  }
}

// ---------------- conversions: fp32 -> bf16 hi/lo planes ---------------------------
__global__ void conv_x_k(const float* __restrict__ x, size_t npair){
  size_t i = (size_t)blockIdx.x * blockDim.x + threadIdx.x;
  if (i >= npair) return;
  float a = x[2*i], b = x[2*i+1];
  __nv_bfloat16 ha = __float2bfloat16(a), hb = __float2bfloat16(b);
  float la = a - __bfloat162float(ha), lb = b - __bfloat162float(hb);
  ((u32*)g_xhi)[i] = (u32)__bfloat16_as_ushort(ha) | ((u32)__bfloat16_as_ushort(hb) << 16);
  ((u32*)g_xlo)[i] = pack2h(la, lb);
}

// w_in [E][D][2F] -> interleaved cols: dst word i covers (g_j, v_j) at cols (2j, 2j+1)
__global__ void conv_win_k(const float* __restrict__ w, int F, size_t n){
  size_t i = (size_t)blockIdx.x * blockDim.x + threadIdx.x;
  if (i >= n) return;                              // n = E*D*F
  size_t row = i / F; int j = (int)(i % F);
  const float* src = w + row * (size_t)(2 * F);
  float a = src[j], b = src[F + j];
  __nv_bfloat16 ha = __float2bfloat16(a), hb = __float2bfloat16(b);
  float la = a - __bfloat162float(ha), lb = b - __bfloat162float(hb);
  ((u32*)g_winhi)[i] = (u32)__bfloat16_as_ushort(ha) | ((u32)__bfloat16_as_ushort(hb) << 16);
  ((u32*)g_winlo)[i] = pack2h(la, lb);
}

__global__ void conv_wout_k(const float* __restrict__ w, size_t npair){
  size_t i = (size_t)blockIdx.x * blockDim.x + threadIdx.x;
  if (i >= npair) return;
  float a = w[2*i], b = w[2*i+1];
  __nv_bfloat16 ha = __float2bfloat16(a), hb = __float2bfloat16(b);
  float la = a - __bfloat162float(ha), lb = b - __bfloat162float(hb);
  ((u32*)g_wouthi)[i] = (u32)__bfloat16_as_ushort(ha) | ((u32)__bfloat16_as_ushort(hb) << 16);
  ((u32*)g_woutlo)[i] = pack2h(la, lb);
}

// ---------------- bf16-split MMA grouped GEMM --------------------------------------
// Block: 512 thr, M=256 x N=128, k-chunk 16, 2-stage cp.async pipeline.
// Warp (16): wm=w>>2 (m 64-tile), wn=w&3 (n 32-tile). mma m16n8k16 row.col.
// acc = Ahi*Bhi + Ahi*Blo + Alo*Bhi (fp32 accumulate).
// GLU=true : A = x rows (token = asg>>1), B = g_win* [e][D][2F], out -> act hi/lo (silu(g)*v)
// GLU=false: A = act rows (assignment), B = g_wout* [e][F][D], out -> g_ybuf fp32
template<bool GLU>
__global__ __launch_bounds__(512, 1)
void moe_gemm_mma(int K, int ldB, int outStride){
  int e = blockIdx.z;
  int count = g_counts[e];
  int m0 = blockIdx.y * 256;
  if (m0 >= count) return;
  int n0 = blockIdx.x * 128;

  extern __shared__ char smem[];
  u32 sb = s2u(smem);
  const u32 STG = 33280u;                 // Ahi 12288 | Alo 12288 | Bhi 4352 | Blo 4352
  int tid = threadIdx.x;

  // ---- fill setup
  int rA = tid >> 1, half = tid & 1;
  const __nv_bfloat16* Ahg = GLU ? g_xhi : g_acthi;
  const __nv_bfloat16* Alg = GLU ? g_xlo : g_actlo;
  const __nv_bfloat16* Bhg = (GLU ? g_winhi : g_wouthi) + (size_t)e * (size_t)K * ldB;
  const __nv_bfloat16* Blg = (GLU ? g_winlo : g_woutlo) + (size_t)e * (size_t)K * ldB;

  bool avalid = (m0 + rA) < count;
  int arow = 0;
  if (avalid){
    int a = g_asg[e * T_MAX + m0 + rA];
    arow = GLU ? (a >> 1) : a;
  }
  const __nv_bfloat16* aph = Ahg + (size_t)arow * K + half * 8;
  const __nv_bfloat16* apl = Alg + (size_t)arow * K + half * 8;
  u32 adst = (u32)rA * 48u + (u32)half * 16u;

  int bplane = tid >> 8, bc = tid & 255, bk = bc >> 4, bcc = bc & 15;
  const __nv_bfloat16* bsrc = (bplane ? Blg : Bhg) + (size_t)bk * ldB + n0 + bcc * 8;
  u32 bdst = 24576u + (u32)bplane * 4352u + (u32)bk * 272u + (u32)bcc * 16u;

  float acc[4][4][4];
  #pragma unroll
  for (int i = 0; i < 4; i++)
    #pragma unroll
    for (int j = 0; j < 4; j++)
      #pragma unroll
      for (int q = 0; q < 4; q++) acc[i][j][q] = 0.f;

  int w = tid >> 5, lane = tid & 31;
  int wm = w >> 2, wn = w & 3;
  u32 aAoff = (u32)(wm * 64 + (lane & 15)) * 48u + (u32)(lane >> 4) * 16u;
  u32 aBoff = (u32)(((lane >> 3) & 1) * 8 + (lane & 7)) * 272u +
              (u32)(wn * 32 + (lane >> 4) * 8) * 2u;

  int C = K / 16;
  // prologue: chunks 0 and 1
  {
    u32 s0 = sb;
    cp16(s0 + adst,          aph, avalid);
    cp16(s0 + adst + 12288u, apl, avalid);
    cp16(s0 + bdst,          bsrc, true);
    CP_COMMIT();
    u32 s1 = sb + STG;
    cp16(s1 + adst,          aph + 16, avalid);
    cp16(s1 + adst + 12288u, apl + 16, avalid);
    cp16(s1 + bdst + 0,      bsrc + (size_t)16 * ldB, true);
    CP_COMMIT();
  }

  for (int c = 0; c < C; c++){
    CP_WAIT1();
    __syncthreads();
    u32 base = sb + (u32)(c & 1) * STG;

    // B fragments for all 4 n-tiles, both planes
    u32 rbh[8], rbl[8];                   // [nt][2] flattened
    #pragma unroll
    for (int bt = 0; bt < 2; bt++){
      LDMX4T(&rbh[bt*4], base + 24576u + aBoff + (u32)bt * 32u);
      LDMX4T(&rbl[bt*4], base + 28928u + aBoff + (u32)bt * 32u);
    }
    #pragma unroll
    for (int mt = 0; mt < 4; mt++){
      u32 aaddr = base + aAoff + (u32)mt * 768u;
      u32 ah[4], al[4];
      LDMX4(ah, aaddr);
      LDMX4(al, aaddr + 12288u);
      #pragma unroll
      for (int nt = 0; nt < 4; nt++) MMA_BF16(acc[mt][nt], ah, rbh[nt*2], rbh[nt*2+1]);
      #pragma unroll
      for (int nt = 0; nt < 4; nt++) MMA_BF16(acc[mt][nt], ah, rbl[nt*2], rbl[nt*2+1]);
      #pragma unroll
      for (int nt = 0; nt < 4; nt++) MMA_BF16(acc[mt][nt], al, rbh[nt*2], rbh[nt*2+1]);
    }
    __syncthreads();
    if (c + 2 < C){
      int k0 = (c + 2) * 16;
      u32 s = sb + (u32)(c & 1) * STG;
      cp16(s + adst,          aph + k0, avalid);
      cp16(s + adst + 12288u, apl + k0, avalid);
      cp16(s + bdst,          bsrc + (size_t)k0 * ldB, true);
    }
    CP_COMMIT();
  }

  // ---- epilogue
  int g = lane >> 2, t = lane & 3;
  #pragma unroll
  for (int mt = 0; mt < 4; mt++){
    int rbase = wm * 64 + mt * 16 + g;
    #pragma unroll
    for (int hrow = 0; hrow < 2; hrow++){
      int mg = m0 + rbase + hrow * 8;
      if (mg >= count) continue;
      int a = g_asg[e * T_MAX + mg];
      if (GLU){
        #pragma unroll
        for (int nt = 0; nt < 4; nt++){
          int j = (n0 >> 1) + wn * 16 + nt * 4 + t;
          float gg = acc[mt][nt][hrow * 2];
          float vv = acc[mt][nt][hrow * 2 + 1];
          float o = (gg / (1.f + __expf(-gg))) * vv;
          __nv_bfloat16 hb = __float2bfloat16(o);
          float lo = o - __bfloat162float(hb);
          g_acthi[(size_t)a * outStride + j] = hb;
          g_actlo[(size_t)a * outStride + j] = __float2bfloat16(lo);
        }
      } else {
        #pragma unroll
        for (int nt = 0; nt < 4; nt++){
          int nc = n0 + wn * 32 + nt * 8 + 2 * t;
          float2 st; st.x = acc[mt][nt][hrow * 2]; st.y = acc[mt][nt][hrow * 2 + 1];
          *(float2*)(g_ybuf + (size_t)a * outStride + nc) = st;
        }
      }
    }
  }
}

// ---------------- combine ----------------------------------------------------------
__global__ void combine_k(const float* __restrict__ bias, float* __restrict__ out,
                          int T, int D, const int* __restrict__ topk_p){
  int t = blockIdx.x;
  int tk = topk_p ? *topk_p : 2;
  if (tk < 1) tk = 1; if (tk > 2) tk = 2;
  for (int c = threadIdx.x * 4; c < D; c += 256 * 4){
    float4 o = *(const float4*)(bias + c);
    #pragma unroll
    for (int k = 0; k < 2; k++){
      if (k < tk){
        float g = g_gates[t*2 + k];
        float4 y = *(const float4*)(g_ybuf + (size_t)(t*2 + k) * D + c);
        o.x += g * y.x; o.y += g * y.y; o.z += g * y.z; o.w += g * y.w;
      }
    }
    *(float4*)(out + (size_t)t * D + c) = o;
  }
}

// ---------------- launch -----------------------------------------------------------
extern "C" void kernel_launch(void* const* d_in, const int* in_sizes, int n_in,
                              void* d_out, int out_size){
  const float* x     = (const float*)d_in[0];
  const float* rw    = (const float*)d_in[1];
  const float* w_in  = (const float*)d_in[2];
  const float* w_out = (const float*)d_in[3];
  const float* bias  = (const float*)d_in[4];
  const int*   topk  = (n_in >= 6) ? (const int*)d_in[5] : nullptr;

  int D = in_sizes[4];
  int T = in_sizes[0] / D;
  int E = in_sizes[1] / D;
  int F = in_sizes[2] / (2 * D * E);
  float* out = (float*)d_out;

  const int SMEM = 2 * 33280;
  static int smem_set = 0;
  if (!smem_set){
    cudaFuncSetAttribute(moe_gemm_mma<true>,  cudaFuncAttributeMaxDynamicSharedMemorySize, SMEM);
    cudaFuncSetAttribute(moe_gemm_mma<false>, cudaFuncAttributeMaxDynamicSharedMemorySize, SMEM);
    smem_set = 1;
  }

  init_k<<<1, 32>>>();
  router_k<<<(T + 7) / 8, 256>>>(x, rw, T, E, D, topk);
  if (out_size > T * D) aux_k<<<1, 1>>>(out + (size_t)T * D, T, E, topk);

  size_t nx = (size_t)T * D / 2;
  conv_x_k<<<(unsigned)((nx + 255) / 256), 256>>>(x, nx);
  size_t nwin = (size_t)E * D * F;
  conv_win_k<<<(unsigned)((nwin + 255) / 256), 256>>>(w_in, F, nwin);
  size_t nwo = (size_t)E * F * D / 2;
  conv_wout_k<<<(unsigned)((nwo + 255) / 256), 256>>>(w_out, nwo);

  int mblocks = (T + 255) / 256;
  dim3 g1((2 * F) / 128, mblocks, E);
  moe_gemm_mma<true><<<g1, 512, SMEM>>>(D, 2 * F, F);

  dim3 g2(D / 128, mblocks, E);
  moe_gemm_mma<false><<<g2, 512, SMEM>>>(F, D, D);

  combine_k<<<T, 256>>>(bias, out, T, D, topk);
}

// round 6
// speedup vs baseline: 1.9942x; 1.2195x over previous
#include <cuda_runtime.h>
#include <cuda_fp16.h>
#include <cstdint>

#define T_MAX 4096
#define E_MAX 8
#define F_MAXC 2048
#define D_MAXC 1024

typedef unsigned int u32;

// ---------------- device scratch ---------------------------------------------------
__device__ int   g_counts[E_MAX];
__device__ float g_Psum[E_MAX];
__device__ int   g_asg[E_MAX * T_MAX];
__device__ float g_gates[T_MAX * 2];
__device__ __half g_xhi [(size_t)T_MAX * D_MAXC];
__device__ __half g_xlo [(size_t)T_MAX * D_MAXC];
__device__ __half g_acthi[(size_t)2 * T_MAX * F_MAXC];
__device__ __half g_actlo[(size_t)2 * T_MAX * F_MAXC];
__device__ __half g_win [(size_t)E_MAX * D_MAXC * 2 * F_MAXC];   // [e][D][2F] interleaved (g,v), fp16
__device__ __half g_wout[(size_t)E_MAX * F_MAXC * D_MAXC];       // [e][F][D] fp16
__device__ float g_ybuf[(size_t)2 * T_MAX * D_MAXC];

// ---------------- helpers ----------------------------------------------------------
__device__ __forceinline__ u32 s2u(const void* p){
  u32 a; asm("{ .reg .u64 t; cvta.to.shared.u64 t, %1; cvt.u32.u64 %0, t; }" : "=r"(a) : "l"(p));
  return a;
}
__device__ __forceinline__ u32 pack2f16(float a, float b){
  __half ha = __float2half_rn(a), hb = __float2half_rn(b);
  return (u32)__half_as_ushort(ha) | ((u32)__half_as_ushort(hb) << 16);
}
__device__ __forceinline__ void cp16(u32 dst, const void* src, bool v){
  int sz = v ? 16 : 0;
  asm volatile("cp.async.cg.shared.global [%0], [%1], 16, %2;" :: "r"(dst), "l"(src), "r"(sz) : "memory");
}
#define CP_COMMIT() asm volatile("cp.async.commit_group;" ::: "memory")
#define CP_WAIT1()  asm volatile("cp.async.wait_group 1;" ::: "memory")

#define LDMX4(r, addr) \
  asm volatile("ldmatrix.sync.aligned.m8n8.x4.shared.b16 {%0,%1,%2,%3}, [%4];" \
    : "=r"((r)[0]), "=r"((r)[1]), "=r"((r)[2]), "=r"((r)[3]) : "r"(addr))
#define LDMX4T(r, addr) \
  asm volatile("ldmatrix.sync.aligned.m8n8.x4.trans.shared.b16 {%0,%1,%2,%3}, [%4];" \
    : "=r"((r)[0]), "=r"((r)[1]), "=r"((r)[2]), "=r"((r)[3]) : "r"(addr))
#define MMA_F16(c, a, b0, b1) \
  asm volatile("mma.sync.aligned.m16n8k16.row.col.f32.f16.f16.f32 " \
    "{%0,%1,%2,%3}, {%4,%5,%6,%7}, {%8,%9}, {%0,%1,%2,%3};" \
    : "+f"((c)[0]), "+f"((c)[1]), "+f"((c)[2]), "+f"((c)[3]) \
    : "r"((a)[0]), "r"((a)[1]), "r"((a)[2]), "r"((a)[3]), "r"(b0), "r"(b1))

// ---------------- init -------------------------------------------------------------
__global__ void init_k(){
  int i = threadIdx.x;
  if (i < E_MAX){ g_counts[i] = 0; g_Psum[i] = 0.f; }
}

// ---------------- router (proven) --------------------------------------------------
__global__ void router_k(const float* __restrict__ x, const float* __restrict__ rw,
                         int T, int E, int D, const int* __restrict__ topk_p){
  int warp = threadIdx.x >> 5, lane = threadIdx.x & 31;
  int t = blockIdx.x * 8 + warp;
  __shared__ float sm_p[8][E_MAX];
  if (lane == 0){
    #pragma unroll
    for (int e = 0; e < E_MAX; e++) sm_p[warp][e] = 0.f;
  }
  if (t < T){
    float acc[E_MAX];
    #pragma unroll
    for (int e = 0; e < E_MAX; e++) acc[e] = 0.f;
    const float* xr = x + (size_t)t * D;
    for (int d = lane; d < D; d += 32){
      float xv = xr[d];
      const float* r = rw + (size_t)d * E;
      #pragma unroll
      for (int e = 0; e < E_MAX; e++) if (e < E) acc[e] += xv * r[e];
    }
    #pragma unroll
    for (int e = 0; e < E_MAX; e++){
      #pragma unroll
      for (int off = 16; off; off >>= 1) acc[e] += __shfl_xor_sync(0xffffffffu, acc[e], off);
    }
    if (lane == 0){
      int tk = topk_p ? *topk_p : 2;
      if (tk < 1) tk = 1; if (tk > 2) tk = 2;
      int i0 = 0; float v0 = acc[0];
      for (int e = 1; e < E; e++) if (acc[e] > v0){ v0 = acc[e]; i0 = e; }
      if (tk == 1){
        g_gates[t*2+0] = 1.f; g_gates[t*2+1] = 0.f;
        int p = atomicAdd(&g_counts[i0], 1);
        g_asg[i0*T_MAX + p] = t*2;
      } else {
        int i1 = -1; float v1 = -3.4e38f;
        for (int e = 0; e < E; e++) if (e != i0 && acc[e] > v1){ v1 = acc[e]; i1 = e; }
        float g1 = 1.f / (1.f + __expf(v0 - v1));
        float g0 = 1.f - g1;
        g_gates[t*2+0] = g0; g_gates[t*2+1] = g1;
        int p0 = atomicAdd(&g_counts[i0], 1); g_asg[i0*T_MAX + p0] = t*2;
        int p1 = atomicAdd(&g_counts[i1], 1); g_asg[i1*T_MAX + p1] = t*2 + 1;
      }
      float m = acc[0];
      for (int e = 1; e < E; e++) m = fmaxf(m, acc[e]);
      float s = 0.f; float pe[E_MAX];
      for (int e = 0; e < E; e++){ pe[e] = __expf(acc[e] - m); s += pe[e]; }
      float inv = 1.f / s;
      for (int e = 0; e < E; e++) sm_p[warp][e] = pe[e] * inv;
    }
  }
  __syncthreads();
  if (threadIdx.x < E){
    float s = 0.f;
    #pragma unroll
    for (int w = 0; w < 8; w++) s += sm_p[w][threadIdx.x];
    atomicAdd(&g_Psum[threadIdx.x], s);
  }
}

__global__ void aux_k(float* dst, int T, int E, const int* __restrict__ topk_p){
  if (threadIdx.x == 0 && blockIdx.x == 0){
    int tk = topk_p ? *topk_p : 2;
    if (tk < 1) tk = 1; if (tk > 2) tk = 2;
    float s = 0.f;
    for (int e = 0; e < E; e++){
      float f = (float)g_counts[e] / (float)(T * tk);
      float P = g_Psum[e] / (float)T;
      s += f * P;
    }
    *dst = (float)E * s;
  }
}

// ---------------- conversions ------------------------------------------------------
// x -> fp16 hi/lo planes (2-limb, exact to ~2^-22)
__global__ void conv_x_k(const float* __restrict__ x, size_t npair){
  size_t i = (size_t)blockIdx.x * blockDim.x + threadIdx.x;
  if (i >= npair) return;
  float a = x[2*i], b = x[2*i+1];
  __half ha = __float2half_rn(a), hb = __float2half_rn(b);
  float la = a - __half2float(ha), lb = b - __half2float(hb);
  ((u32*)g_xhi)[i] = (u32)__half_as_ushort(ha) | ((u32)__half_as_ushort(hb) << 16);
  ((u32*)g_xlo)[i] = pack2f16(la, lb);
}

// w_in [E][D][2F] -> single fp16 plane with interleaved cols: word i = (g_j, v_j)
__global__ void conv_win_k(const float* __restrict__ w, int F, size_t n){
  size_t i = (size_t)blockIdx.x * blockDim.x + threadIdx.x;
  if (i >= n) return;                              // n = E*D*F
  size_t row = i / F; int j = (int)(i % F);
  const float* src = w + row * (size_t)(2 * F);
  ((u32*)g_win)[i] = pack2f16(src[j], src[F + j]);
}

// w_out -> single fp16 plane
__global__ void conv_wout_k(const float* __restrict__ w, size_t npair){
  size_t i = (size_t)blockIdx.x * blockDim.x + threadIdx.x;
  if (i >= npair) return;
  ((u32*)g_wout)[i] = pack2f16(w[2*i], w[2*i+1]);
}

// ---------------- fp16 2-limb MMA grouped GEMM ------------------------------------
// Block: 512 thr, M=256 x N=128, k-chunk 16, 2-stage cp.async pipeline.
// acc = Ahi*B + Alo*B  (A exact to 2^-22; error = a·(b - fp16(b)) ~ 2e-4)
// GLU=true : A = x rows (token = asg>>1), B = g_win [e][D][2F], out -> act hi/lo (silu(g)*v)
// GLU=false: A = act rows (assignment), B = g_wout [e][F][D], out -> g_ybuf fp32
template<bool GLU>
__global__ __launch_bounds__(512, 1)
void moe_gemm_mma(int K, int ldB, int outStride){
  int e = blockIdx.z;
  int count = g_counts[e];
  int m0 = blockIdx.y * 256;
  if (m0 >= count) return;
  int n0 = blockIdx.x * 128;

  extern __shared__ char smem[];
  u32 sb = s2u(smem);
  const u32 STG = 28928u;                 // Ahi 12288 | Alo 12288 | B 4352
  int tid = threadIdx.x;

  // ---- fill setup
  int rA = tid >> 1, half = tid & 1;
  const __half* Ahg = GLU ? g_xhi : g_acthi;
  const __half* Alg = GLU ? g_xlo : g_actlo;
  const __half* Bg  = (GLU ? g_win : g_wout) + (size_t)e * (size_t)K * ldB;

  bool avalid = (m0 + rA) < count;
  int arow = 0;
  if (avalid){
    int a = g_asg[e * T_MAX + m0 + rA];
    arow = GLU ? (a >> 1) : a;
  }
  const __half* aph = Ahg + (size_t)arow * K + half * 8;
  const __half* apl = Alg + (size_t)arow * K + half * 8;
  u32 adst = (u32)rA * 48u + (u32)half * 16u;

  bool bfill = tid < 256;
  int bk = (tid >> 4) & 15, bcc = tid & 15;
  const __half* bsrc = Bg + (size_t)bk * ldB + n0 + bcc * 8;
  u32 bdst = 24576u + (u32)bk * 272u + (u32)bcc * 16u;

  float acc[4][4][4];
  #pragma unroll
  for (int i = 0; i < 4; i++)
    #pragma unroll
    for (int j = 0; j < 4; j++)
      #pragma unroll
      for (int q = 0; q < 4; q++) acc[i][j][q] = 0.f;

  int w = tid >> 5, lane = tid & 31;
  int wm = w >> 2, wn = w & 3;
  u32 aAoff = (u32)(wm * 64 + (lane & 15)) * 48u + (u32)(lane >> 4) * 16u;
  u32 aBoff = (u32)(((lane >> 3) & 1) * 8 + (lane & 7)) * 272u +
              (u32)(wn * 32 + (lane >> 4) * 8) * 2u;

  int C = K / 16;
  // prologue: chunks 0 and 1
  {
    u32 s0 = sb;
    cp16(s0 + adst,          aph, avalid);
    cp16(s0 + adst + 12288u, apl, avalid);
    if (bfill) cp16(s0 + bdst, bsrc, true);
    CP_COMMIT();
    u32 s1 = sb + STG;
    cp16(s1 + adst,          aph + 16, avalid);
    cp16(s1 + adst + 12288u, apl + 16, avalid);
    if (bfill) cp16(s1 + bdst, bsrc + (size_t)16 * ldB, true);
    CP_COMMIT();
  }

  for (int c = 0; c < C; c++){
    CP_WAIT1();
    __syncthreads();
    u32 base = sb + (u32)(c & 1) * STG;

    // B fragments for all 4 n-tiles (single plane)
    u32 rb[8];
    #pragma unroll
    for (int bt = 0; bt < 2; bt++)
      LDMX4T(&rb[bt*4], base + 24576u + aBoff + (u32)bt * 32u);

    #pragma unroll
    for (int mt = 0; mt < 4; mt++){
      u32 aaddr = base + aAoff + (u32)mt * 768u;
      u32 ah[4], al[4];
      LDMX4(ah, aaddr);
      LDMX4(al, aaddr + 12288u);
      #pragma unroll
      for (int nt = 0; nt < 4; nt++) MMA_F16(acc[mt][nt], ah, rb[nt*2], rb[nt*2+1]);
      #pragma unroll
      for (int nt = 0; nt < 4; nt++) MMA_F16(acc[mt][nt], al, rb[nt*2], rb[nt*2+1]);
    }
    __syncthreads();
    if (c + 2 < C){
      int k0 = (c + 2) * 16;
      u32 s = sb + (u32)(c & 1) * STG;
      cp16(s + adst,          aph + k0, avalid);
      cp16(s + adst + 12288u, apl + k0, avalid);
      if (bfill) cp16(s + bdst, bsrc + (size_t)k0 * ldB, true);
    }
    CP_COMMIT();
  }

  // ---- epilogue
  int g = lane >> 2, t = lane & 3;
  #pragma unroll
  for (int mt = 0; mt < 4; mt++){
    int rbase = wm * 64 + mt * 16 + g;
    #pragma unroll
    for (int hrow = 0; hrow < 2; hrow++){
      int mg = m0 + rbase + hrow * 8;
      if (mg >= count) continue;
      int a = g_asg[e * T_MAX + mg];
      if (GLU){
        #pragma unroll
        for (int nt = 0; nt < 4; nt++){
          int j = (n0 >> 1) + wn * 16 + nt * 4 + t;
          float gg = acc[mt][nt][hrow * 2];
          float vv = acc[mt][nt][hrow * 2 + 1];
          float o = (gg / (1.f + __expf(-gg))) * vv;
          __half hb = __float2half_rn(o);
          float lo = o - __half2float(hb);
          g_acthi[(size_t)a * outStride + j] = hb;
          g_actlo[(size_t)a * outStride + j] = __float2half_rn(lo);
        }
      } else {
        #pragma unroll
        for (int nt = 0; nt < 4; nt++){
          int nc = n0 + wn * 32 + nt * 8 + 2 * t;
          float2 st; st.x = acc[mt][nt][hrow * 2]; st.y = acc[mt][nt][hrow * 2 + 1];
          *(float2*)(g_ybuf + (size_t)a * outStride + nc) = st;
        }
      }
    }
  }
}

// ---------------- combine ----------------------------------------------------------
__global__ void combine_k(const float* __restrict__ bias, float* __restrict__ out,
                          int T, int D, const int* __restrict__ topk_p){
  int t = blockIdx.x;
  int tk = topk_p ? *topk_p : 2;
  if (tk < 1) tk = 1; if (tk > 2) tk = 2;
  for (int c = threadIdx.x * 4; c < D; c += 256 * 4){
    float4 o = *(const float4*)(bias + c);
    #pragma unroll
    for (int k = 0; k < 2; k++){
      if (k < tk){
        float g = g_gates[t*2 + k];
        float4 y = *(const float4*)(g_ybuf + (size_t)(t*2 + k) * D + c);
        o.x += g * y.x; o.y += g * y.y; o.z += g * y.z; o.w += g * y.w;
      }
    }
    *(float4*)(out + (size_t)t * D + c) = o;
  }
}

// ---------------- launch -----------------------------------------------------------
extern "C" void kernel_launch(void* const* d_in, const int* in_sizes, int n_in,
                              void* d_out, int out_size){
  const float* x     = (const float*)d_in[0];
  const float* rw    = (const float*)d_in[1];
  const float* w_in  = (const float*)d_in[2];
  const float* w_out = (const float*)d_in[3];
  const float* bias  = (const float*)d_in[4];
  const int*   topk  = (n_in >= 6) ? (const int*)d_in[5] : nullptr;

  int D = in_sizes[4];
  int T = in_sizes[0] / D;
  int E = in_sizes[1] / D;
  int F = in_sizes[2] / (2 * D * E);
  float* out = (float*)d_out;

  const int SMEM = 2 * 28928;
  cudaFuncSetAttribute(moe_gemm_mma<true>,  cudaFuncAttributeMaxDynamicSharedMemorySize, SMEM);
  cudaFuncSetAttribute(moe_gemm_mma<false>, cudaFuncAttributeMaxDynamicSharedMemorySize, SMEM);

  init_k<<<1, 32>>>();
  router_k<<<(T + 7) / 8, 256>>>(x, rw, T, E, D, topk);
  if (out_size > T * D) aux_k<<<1, 1>>>(out + (size_t)T * D, T, E, topk);

  size_t nx = (size_t)T * D / 2;
  conv_x_k<<<(unsigned)((nx + 255) / 256), 256>>>(x, nx);
  size_t nwin = (size_t)E * D * F;
  conv_win_k<<<(unsigned)((nwin + 255) / 256), 256>>>(w_in, F, nwin);
  size_t nwo = (size_t)E * F * D / 2;
  conv_wout_k<<<(unsigned)((nwo + 255) / 256), 256>>>(w_out, nwo);

  int mblocks = (T + 255) / 256;
  dim3 g1((2 * F) / 128, mblocks, E);
  moe_gemm_mma<true><<<g1, 512, SMEM>>>(D, 2 * F, F);

  dim3 g2(D / 128, mblocks, E);
  moe_gemm_mma<false><<<g2, 512, SMEM>>>(F, D, D);

  combine_k<<<T, 256>>>(bias, out, T, D, topk);
}

// round 8
// speedup vs baseline: 3.1866x; 1.5979x over previous
#include <cuda_runtime.h>
#include <cuda_fp16.h>
#include <cstdint>

#define T_MAX 4096
#define E_MAX 8
#define F_MAXC 2048
#define D_MAXC 1024

typedef unsigned int u32;

// ---------------- device scratch ---------------------------------------------------
__device__ int   g_counts[E_MAX];
__device__ float g_Psum[E_MAX];
__device__ int   g_asg[E_MAX * T_MAX];
__device__ float g_gates[T_MAX * 2];
__device__ __half g_xh  [(size_t)T_MAX * D_MAXC];                // fp16 x
__device__ __half g_act [(size_t)2 * T_MAX * F_MAXC];            // fp16 silu(g)*v
__device__ __half g_win [(size_t)E_MAX * D_MAXC * 2 * F_MAXC];   // [e][D][2F] interleaved (g,v)
__device__ __half g_wout[(size_t)E_MAX * F_MAXC * D_MAXC];       // [e][F][D]
__device__ float g_ybuf[(size_t)2 * T_MAX * D_MAXC];

// ---------------- helpers ----------------------------------------------------------
__device__ __forceinline__ u32 s2u(const void* p){
  u32 a; asm("{ .reg .u64 t; cvta.to.shared.u64 t, %1; cvt.u32.u64 %0, t; }" : "=r"(a) : "l"(p));
  return a;
}
__device__ __forceinline__ u32 pack2f16(float a, float b){
  __half ha = __float2half_rn(a), hb = __float2half_rn(b);
  return (u32)__half_as_ushort(ha) | ((u32)__half_as_ushort(hb) << 16);
}
__device__ __forceinline__ void cp16(u32 dst, const void* src, bool v){
  int sz = v ? 16 : 0;
  asm volatile("cp.async.cg.shared.global [%0], [%1], 16, %2;" :: "r"(dst), "l"(src), "r"(sz) : "memory");
}
#define CP_COMMIT() asm volatile("cp.async.commit_group;" ::: "memory")
#define CP_WAIT1()  asm volatile("cp.async.wait_group 1;" ::: "memory")

#define LDMX4(r, addr) \
  asm volatile("ldmatrix.sync.aligned.m8n8.x4.shared.b16 {%0,%1,%2,%3}, [%4];" \
    : "=r"((r)[0]), "=r"((r)[1]), "=r"((r)[2]), "=r"((r)[3]) : "r"(addr))
#define LDMX4T(r, addr) \
  asm volatile("ldmatrix.sync.aligned.m8n8.x4.trans.shared.b16 {%0,%1,%2,%3}, [%4];" \
    : "=r"((r)[0]), "=r"((r)[1]), "=r"((r)[2]), "=r"((r)[3]) : "r"(addr))
#define MMA_F16(c, a, b0, b1) \
  asm volatile("mma.sync.aligned.m16n8k16.row.col.f32.f16.f16.f32 " \
    "{%0,%1,%2,%3}, {%4,%5,%6,%7}, {%8,%9}, {%0,%1,%2,%3};" \
    : "+f"((c)[0]), "+f"((c)[1]), "+f"((c)[2]), "+f"((c)[3]) \
    : "r"((a)[0]), "r"((a)[1]), "r"((a)[2]), "r"((a)[3]), "r"(b0), "r"(b1))

// ---------------- init -------------------------------------------------------------
__global__ void init_k(){
  int i = threadIdx.x;
  if (i < E_MAX){ g_counts[i] = 0; g_Psum[i] = 0.f; }
}

// ---------------- router (proven) --------------------------------------------------
__global__ void router_k(const float* __restrict__ x, const float* __restrict__ rw,
                         int T, int E, int D, const int* __restrict__ topk_p){
  int warp = threadIdx.x >> 5, lane = threadIdx.x & 31;
  int t = blockIdx.x * 8 + warp;
  __shared__ float sm_p[8][E_MAX];
  if (lane == 0){
    #pragma unroll
    for (int e = 0; e < E_MAX; e++) sm_p[warp][e] = 0.f;
  }
  if (t < T){
    float acc[E_MAX];
    #pragma unroll
    for (int e = 0; e < E_MAX; e++) acc[e] = 0.f;
    const float* xr = x + (size_t)t * D;
    for (int d = lane; d < D; d += 32){
      float xv = xr[d];
      const float* r = rw + (size_t)d * E;
      #pragma unroll
      for (int e = 0; e < E_MAX; e++) if (e < E) acc[e] += xv * r[e];
    }
    #pragma unroll
    for (int e = 0; e < E_MAX; e++){
      #pragma unroll
      for (int off = 16; off; off >>= 1) acc[e] += __shfl_xor_sync(0xffffffffu, acc[e], off);
    }
    if (lane == 0){
      int tk = topk_p ? *topk_p : 2;
      if (tk < 1) tk = 1; if (tk > 2) tk = 2;
      int i0 = 0; float v0 = acc[0];
      for (int e = 1; e < E; e++) if (acc[e] > v0){ v0 = acc[e]; i0 = e; }
      if (tk == 1){
        g_gates[t*2+0] = 1.f; g_gates[t*2+1] = 0.f;
        int p = atomicAdd(&g_counts[i0], 1);
        g_asg[i0*T_MAX + p] = t*2;
      } else {
        int i1 = -1; float v1 = -3.4e38f;
        for (int e = 0; e < E; e++) if (e != i0 && acc[e] > v1){ v1 = acc[e]; i1 = e; }
        float g1 = 1.f / (1.f + __expf(v0 - v1));
        float g0 = 1.f - g1;
        g_gates[t*2+0] = g0; g_gates[t*2+1] = g1;
        int p0 = atomicAdd(&g_counts[i0], 1); g_asg[i0*T_MAX + p0] = t*2;
        int p1 = atomicAdd(&g_counts[i1], 1); g_asg[i1*T_MAX + p1] = t*2 + 1;
      }
      float m = acc[0];
      for (int e = 1; e < E; e++) m = fmaxf(m, acc[e]);
      float s = 0.f; float pe[E_MAX];
      for (int e = 0; e < E; e++){ pe[e] = __expf(acc[e] - m); s += pe[e]; }
      float inv = 1.f / s;
      for (int e = 0; e < E; e++) sm_p[warp][e] = pe[e] * inv;
    }
  }
  __syncthreads();
  if (threadIdx.x < E){
    float s = 0.f;
    #pragma unroll
    for (int w = 0; w < 8; w++) s += sm_p[w][threadIdx.x];
    atomicAdd(&g_Psum[threadIdx.x], s);
  }
}

__global__ void aux_k(float* dst, int T, int E, const int* __restrict__ topk_p){
  if (threadIdx.x == 0 && blockIdx.x == 0){
    int tk = topk_p ? *topk_p : 2;
    if (tk < 1) tk = 1; if (tk > 2) tk = 2;
    float s = 0.f;
    for (int e = 0; e < E; e++){
      float f = (float)g_counts[e] / (float)(T * tk);
      float P = g_Psum[e] / (float)T;
      s += f * P;
    }
    *dst = (float)E * s;
  }
}

// ---------------- conversions ------------------------------------------------------
__global__ void conv_x_k(const float* __restrict__ x, size_t npair){
  size_t i = (size_t)blockIdx.x * blockDim.x + threadIdx.x;
  if (i >= npair) return;
  ((u32*)g_xh)[i] = pack2f16(x[2*i], x[2*i+1]);
}

// w_in [E][D][2F] -> fp16 with interleaved cols: word i = (g_j, v_j)
__global__ void conv_win_k(const float* __restrict__ w, int F, size_t n){
  size_t i = (size_t)blockIdx.x * blockDim.x + threadIdx.x;
  if (i >= n) return;                              // n = E*D*F
  size_t row = i / F; int j = (int)(i % F);
  const float* src = w + row * (size_t)(2 * F);
  ((u32*)g_win)[i] = pack2f16(src[j], src[F + j]);
}

__global__ void conv_wout_k(const float* __restrict__ w, size_t npair){
  size_t i = (size_t)blockIdx.x * blockDim.x + threadIdx.x;
  if (i >= npair) return;
  ((u32*)g_wout)[i] = pack2f16(w[2*i], w[2*i+1]);
}

// ---------------- fp16 single-plane MMA grouped GEMM ------------------------------
// Block: 512 thr, M=256 x N=128, k-chunk 16, 2-stage cp.async pipeline.
// GLU=true : A = x rows (token = asg>>1), B = g_win [e][D][2F], out -> g_act (silu(g)*v)
// GLU=false: A = g_act rows (assignment), B = g_wout [e][F][D], out -> g_ybuf fp32
template<bool GLU>
__global__ __launch_bounds__(512, 1)
void moe_gemm_mma(int K, int ldB, int outStride){
  int e = blockIdx.z;
  int count = g_counts[e];
  int m0 = blockIdx.y * 256;
  if (m0 >= count) return;
  int n0 = blockIdx.x * 128;

  extern __shared__ char smem[];
  u32 sb = s2u(smem);
  const u32 STG = 16640u;                 // A 12288 | B 4352
  int tid = threadIdx.x;

  // ---- fill setup
  int rA = tid >> 1, half = tid & 1;
  const __half* Ahg = GLU ? g_xh : g_act;
  const __half* Bg  = (GLU ? g_win : g_wout) + (size_t)e * (size_t)K * ldB;

  bool avalid = (m0 + rA) < count;
  int arow = 0;
  if (avalid){
    int a = g_asg[e * T_MAX + m0 + rA];
    arow = GLU ? (a >> 1) : a;
  }
  const __half* aph = Ahg + (size_t)arow * K + half * 8;
  u32 adst = (u32)rA * 48u + (u32)half * 16u;

  bool bfill = tid < 256;
  int bk = (tid >> 4) & 15, bcc = tid & 15;
  const __half* bsrc = Bg + (size_t)bk * ldB + n0 + bcc * 8;
  u32 bdst = 12288u + (u32)bk * 272u + (u32)bcc * 16u;

  float acc[4][4][4];
  #pragma unroll
  for (int i = 0; i < 4; i++)
    #pragma unroll
    for (int j = 0; j < 4; j++)
      #pragma unroll
      for (int q = 0; q < 4; q++) acc[i][j][q] = 0.f;

  int w = tid >> 5, lane = tid & 31;
  int wm = w >> 2, wn = w & 3;
  u32 aAoff = (u32)(wm * 64 + (lane & 15)) * 48u + (u32)(lane >> 4) * 16u;
  u32 aBoff = (u32)(((lane >> 3) & 1) * 8 + (lane & 7)) * 272u +
              (u32)(wn * 32 + (lane >> 4) * 8) * 2u;

  int C = K / 16;
  // prologue: chunks 0 and 1
  {
    u32 s0 = sb;
    cp16(s0 + adst, aph, avalid);
    if (bfill) cp16(s0 + bdst, bsrc, true);
    CP_COMMIT();
    u32 s1 = sb + STG;
    cp16(s1 + adst, aph + 16, avalid);
    if (bfill) cp16(s1 + bdst, bsrc + (size_t)16 * ldB, true);
    CP_COMMIT();
  }

  for (int c = 0; c < C; c++){
    CP_WAIT1();
    __syncthreads();
    u32 base = sb + (u32)(c & 1) * STG;

    // B fragments for all 4 n-tiles
    u32 rb[8];
    #pragma unroll
    for (int bt = 0; bt < 2; bt++)
      LDMX4T(&rb[bt*4], base + 12288u + aBoff + (u32)bt * 32u);

    #pragma unroll
    for (int mt = 0; mt < 4; mt++){
      u32 ah[4];
      LDMX4(ah, base + aAoff + (u32)mt * 768u);
      #pragma unroll
      for (int nt = 0; nt < 4; nt++) MMA_F16(acc[mt][nt], ah, rb[nt*2], rb[nt*2+1]);
    }
    __syncthreads();
    if (c + 2 < C){
      int k0 = (c + 2) * 16;
      u32 s = sb + (u32)(c & 1) * STG;
      cp16(s + adst, aph + k0, avalid);
      if (bfill) cp16(s + bdst, bsrc + (size_t)k0 * ldB, true);
    }
    CP_COMMIT();
  }

  // ---- epilogue
  int g = lane >> 2, t = lane & 3;
  #pragma unroll
  for (int mt = 0; mt < 4; mt++){
    int rbase = wm * 64 + mt * 16 + g;
    #pragma unroll
    for (int hrow = 0; hrow < 2; hrow++){
      int mg = m0 + rbase + hrow * 8;
      if (mg >= count) continue;
      int a = g_asg[e * T_MAX + mg];
      if (GLU){
        #pragma unroll
        for (int nt = 0; nt < 4; nt++){
          int j = (n0 >> 1) + wn * 16 + nt * 4 + t;
          float gg = acc[mt][nt][hrow * 2];
          float vv = acc[mt][nt][hrow * 2 + 1];
          float o = (gg / (1.f + __expf(-gg))) * vv;
          g_act[(size_t)a * outStride + j] = __float2half_rn(o);
        }
      } else {
        #pragma unroll
        for (int nt = 0; nt < 4; nt++){
          int nc = n0 + wn * 32 + nt * 8 + 2 * t;
          float2 st; st.x = acc[mt][nt][hrow * 2]; st.y = acc[mt][nt][hrow * 2 + 1];
          *(float2*)(g_ybuf + (size_t)a * outStride + nc) = st;
        }
      }
    }
  }
}

// ---------------- combine ----------------------------------------------------------
__global__ void combine_k(const float* __restrict__ bias, float* __restrict__ out,
                          int T, int D, const int* __restrict__ topk_p){
  int t = blockIdx.x;
  int tk = topk_p ? *topk_p : 2;
  if (tk < 1) tk = 1; if (tk > 2) tk = 2;
  for (int c = threadIdx.x * 4; c < D; c += 256 * 4){
    float4 o = *(const float4*)(bias + c);
    #pragma unroll
    for (int k = 0; k < 2; k++){
      if (k < tk){
        float g = g_gates[t*2 + k];
        float4 y = *(const float4*)(g_ybuf + (size_t)(t*2 + k) * D + c);
        o.x += g * y.x; o.y += g * y.y; o.z += g * y.z; o.w += g * y.w;
      }
    }
    *(float4*)(out + (size_t)t * D + c) = o;
  }
}

// ---------------- launch -----------------------------------------------------------
extern "C" void kernel_launch(void* const* d_in, const int* in_sizes, int n_in,
                              void* d_out, int out_size){
  const float* x     = (const float*)d_in[0];
  const float* rw    = (const float*)d_in[1];
  const float* w_in  = (const float*)d_in[2];
  const float* w_out = (const float*)d_in[3];
  const float* bias  = (const float*)d_in[4];
  const int*   topk  = (n_in >= 6) ? (const int*)d_in[5] : nullptr;

  int D = in_sizes[4];
  int T = in_sizes[0] / D;
  int E = in_sizes[1] / D;
  int F = in_sizes[2] / (2 * D * E);
  float* out = (float*)d_out;

  const int SMEM = 2 * 16640;
  cudaFuncSetAttribute(moe_gemm_mma<true>,  cudaFuncAttributeMaxDynamicSharedMemorySize, SMEM);
  cudaFuncSetAttribute(moe_gemm_mma<false>, cudaFuncAttributeMaxDynamicSharedMemorySize, SMEM);

  init_k<<<1, 32>>>();
  router_k<<<(T + 7) / 8, 256>>>(x, rw, T, E, D, topk);
  if (out_size > T * D) aux_k<<<1, 1>>>(out + (size_t)T * D, T, E, topk);

  size_t nx = (size_t)T * D / 2;
  conv_x_k<<<(unsigned)((nx + 255) / 256), 256>>>(x, nx);
  size_t nwin = (size_t)E * D * F;
  conv_win_k<<<(unsigned)((nwin + 255) / 256), 256>>>(w_in, F, nwin);
  size_t nwo = (size_t)E * F * D / 2;
  conv_wout_k<<<(unsigned)((nwo + 255) / 256), 256>>>(w_out, nwo);

  int mblocks = (T + 255) / 256;
  dim3 g1((2 * F) / 128, mblocks, E);
  moe_gemm_mma<true><<<g1, 512, SMEM>>>(D, 2 * F, F);

  dim3 g2(D / 128, mblocks, E);
  moe_gemm_mma<false><<<g2, 512, SMEM>>>(F, D, D);

  combine_k<<<T, 256>>>(bias, out, T, D, topk);
}